// round 2
// baseline (speedup 1.0000x reference)
#include <cuda_runtime.h>
#include <math.h>

// ---------------- problem constants ----------------
#define B_    32
#define LT_   64
#define LS_   256
#define NTOK  320      // LT + LS
#define DIM_  768
#define H_    12
#define DH    64
#define LK_   180      // kept source tokens
#define LR_   76       // removed
#define N2    244      // LT + LK

// ---------------- scratch (device globals; no allocs allowed) ----------------
__device__ float g_XLN [B_ * NTOK * DIM_];
__device__ float g_QKV [B_ * NTOK * 3 * DIM_];
__device__ float g_ATTN[(size_t)B_ * H_ * NTOK * NTOK];
__device__ float g_O   [B_ * NTOK * DIM_];
__device__ float g_X1  [B_ * NTOK * DIM_];
__device__ float g_S   [B_ * LS_];
__device__ int   g_ORD [B_ * LS_];
__device__ float g_X2  [B_ * N2 * DIM_];
__device__ float g_XLN2[B_ * N2 * DIM_];
__device__ float g_H1  [B_ * N2 * 4 * DIM_];

// ---------------- GEMM: C = act(alpha*A@B(^T) + bias + Res) ----------------
// All M,N multiples of 64 and K multiples of 16 in this problem -> no bounds checks.
#define BM 64
#define BN 64
#define BK 16

template<bool TRANSB, int ACT, bool KAHAN>   // ACT: 0 = none, 1 = exact GELU
__global__ __launch_bounds__(256)
void gemm_kernel(const float* __restrict__ A, int lda, long long sA1, long long sA2,
                 const float* __restrict__ Bm, int ldb, long long sB1, long long sB2,
                 float* __restrict__ C, int ldc, long long sC1, long long sC2,
                 const float* __restrict__ bias,
                 const float* __restrict__ Res, int ldr, long long sR1, long long sR2,
                 int K, int bdiv, float alpha)
{
    __shared__ float As[BK][BM + 4];
    __shared__ float Bs[BK][BN + 4];

    int bz = blockIdx.z;
    int ob = bz / bdiv;
    int ib = bz - ob * bdiv;
    A  += ob * sA1 + ib * sA2;
    Bm += ob * sB1 + ib * sB2;
    C  += ob * sC1 + ib * sC2;
    if (Res) Res += ob * sR1 + ib * sR2;

    int bm = blockIdx.y * BM;
    int bn = blockIdx.x * BN;
    int tid = threadIdx.x;
    int tx = tid & 15, ty = tid >> 4;

    float acc[4][4] = {};
    float cmp[4][4] = {};   // Kahan compensation

    for (int k0 = 0; k0 < K; k0 += BK) {
        #pragma unroll
        for (int i = 0; i < 4; i++) {
            int idx = tid + i * 256;
            int m  = idx >> 4;
            int kk = idx & 15;
            As[kk][m] = A[(long long)(bm + m) * lda + k0 + kk];
        }
        if (TRANSB) {
            #pragma unroll
            for (int i = 0; i < 4; i++) {
                int idx = tid + i * 256;
                int n  = idx >> 4;
                int kk = idx & 15;
                Bs[kk][n] = Bm[(long long)(bn + n) * ldb + k0 + kk];
            }
        } else {
            #pragma unroll
            for (int i = 0; i < 4; i++) {
                int idx = tid + i * 256;
                int kk = idx >> 6;
                int n  = idx & 63;
                Bs[kk][n] = Bm[(long long)(k0 + kk) * ldb + bn + n];
            }
        }
        __syncthreads();

        #pragma unroll
        for (int kk = 0; kk < BK; kk++) {
            float4 av = *(const float4*)&As[kk][ty * 4];
            float4 bv = *(const float4*)&Bs[kk][tx * 4];
            float a4[4] = {av.x, av.y, av.z, av.w};
            float b4[4] = {bv.x, bv.y, bv.z, bv.w};
            #pragma unroll
            for (int i = 0; i < 4; i++)
                #pragma unroll
                for (int j = 0; j < 4; j++) {
                    if (KAHAN) {
                        // compensated: y = a*b - cmp (single-rounded via FMA),
                        // t = acc + y, cmp = (t - acc) - y, acc = t
                        float y = __fmaf_rn(a4[i], b4[j], -cmp[i][j]);
                        float t = acc[i][j] + y;
                        cmp[i][j] = (t - acc[i][j]) - y;
                        acc[i][j] = t;
                    } else {
                        acc[i][j] = __fmaf_rn(a4[i], b4[j], acc[i][j]);
                    }
                }
        }
        __syncthreads();
    }

    #pragma unroll
    for (int i = 0; i < 4; i++) {
        int m = bm + ty * 4 + i;
        #pragma unroll
        for (int j = 0; j < 4; j++) {
            int n = bn + tx * 4 + j;
            float v = acc[i][j] * alpha;
            if (bias) v += bias[n];
            if (Res)  v += Res[(long long)m * ldr + n];
            if (ACT == 1) v = 0.5f * v * (1.0f + erff(v * 0.70710678118654752f));
            C[(long long)m * ldc + n] = v;
        }
    }
}

// ---------------- LayerNorm (row = 768), fp64 statistics ----------------
__global__ __launch_bounds__(256)
void ln_kernel(const float* __restrict__ x, const float* __restrict__ g,
               const float* __restrict__ b, float* __restrict__ y)
{
    long long row = blockIdx.x;
    const float* xr = x + row * DIM_;
    float* yr = y + row * DIM_;
    int t = threadIdx.x;
    float v0 = xr[t], v1 = xr[t + 256], v2 = xr[t + 512];
    double s = (double)v0 + (double)v1 + (double)v2;
    double q = (double)v0 * v0 + (double)v1 * v1 + (double)v2 * v2;
    __shared__ double sh[16];
    __shared__ float  par[2];
    #pragma unroll
    for (int o = 16; o > 0; o >>= 1) {
        s += __shfl_down_sync(~0u, s, o);
        q += __shfl_down_sync(~0u, q, o);
    }
    int wid = t >> 5, lane = t & 31;
    if (lane == 0) { sh[wid] = s; sh[wid + 8] = q; }
    __syncthreads();
    if (t == 0) {
        double ss = 0., qq = 0.;
        #pragma unroll
        for (int i = 0; i < 8; i++) { ss += sh[i]; qq += sh[i + 8]; }
        double mu = ss / DIM_;
        double var = qq / DIM_ - mu * mu;
        par[0] = (float)mu;
        par[1] = (float)(1.0 / sqrt(var + 1e-5));
    }
    __syncthreads();
    float mu = par[0], r = par[1];
    yr[t]       = (v0 - mu) * r * g[t]       + b[t];
    yr[t + 256] = (v1 - mu) * r * g[t + 256] + b[t + 256];
    yr[t + 512] = (v2 - mu) * r * g[t + 512] + b[t + 512];
}

// ---------------- row softmax over 320, fp64 exp/sum ----------------
__global__ __launch_bounds__(128)
void softmax_kernel(float* __restrict__ attn)
{
    long long row = blockIdx.x;
    float* p = attn + row * NTOK;
    int t = threadIdx.x;
    float v[3];
    float m = -1e30f;
    #pragma unroll
    for (int i = 0; i < 3; i++) {
        int c = t + i * 128;
        v[i] = (c < NTOK) ? p[c] : -1e30f;
        m = fmaxf(m, v[i]);
    }
    __shared__ float shm[4];
    __shared__ double shd[4];
    #pragma unroll
    for (int o = 16; o > 0; o >>= 1) m = fmaxf(m, __shfl_xor_sync(~0u, m, o));
    if ((t & 31) == 0) shm[t >> 5] = m;
    __syncthreads();
    m = fmaxf(fmaxf(shm[0], shm[1]), fmaxf(shm[2], shm[3]));
    __syncthreads();
    double e[3];
    double s = 0.0;
    #pragma unroll
    for (int i = 0; i < 3; i++) {
        int c = t + i * 128;
        if (c < NTOK) { e[i] = exp((double)v[i] - (double)m); s += e[i]; }
        else e[i] = 0.0;
    }
    #pragma unroll
    for (int o = 16; o > 0; o >>= 1) s += __shfl_xor_sync(~0u, s, o);
    if ((t & 31) == 0) shd[t >> 5] = s;
    __syncthreads();
    s = shd[0] + shd[1] + shd[2] + shd[3];
    double inv = 1.0 / s;
    #pragma unroll
    for (int i = 0; i < 3; i++) {
        int c = t + i * 128;
        if (c < NTOK) p[c] = (float)(e[i] * inv);
    }
}

// ---------------- CE scores (fp64 accumulation) ----------------
// mask dtype is ambiguous (bool may be delivered as uint8 / int32 / float32).
// Detect deterministically from the first 2048 bytes (always within bounds).
__global__ __launch_bounds__(256)
void ce_score_kernel(const float* __restrict__ attn, const unsigned char* __restrict__ maskp,
                     float* __restrict__ S)
{
    int b = blockIdx.x;
    int j = threadIdx.x;
    __shared__ float mf[LT_];
    __shared__ double cntsh;
    __shared__ int mode; // 0 = int32, 1 = float32, 2 = uint8
    if (j == 0) {
        const unsigned int* w = (const unsigned int*)maskp;
        bool all_int = true, all_flt = true;
        for (int i = 0; i < 512; i++) {
            unsigned int v = w[i];
            if (v != 0u && v != 1u) all_int = false;
            if (v != 0u && v != 0x3F800000u) all_flt = false;
        }
        mode = all_int ? 0 : (all_flt ? 1 : 2);
    }
    __syncthreads();
    if (j < LT_) {
        int mv;
        if (mode == 0)      mv = ((const int*)maskp)[b * LT_ + j] != 0;
        else if (mode == 1) mv = ((const float*)maskp)[b * LT_ + j] != 0.0f;
        else                mv = maskp[b * LT_ + j] != 0;
        mf[j] = mv ? 1.0f : 0.0f;
    }
    __syncthreads();
    if (j == 0) {
        double c = 0.;
        for (int t = 0; t < LT_; t++) c += (double)mf[t];
        cntsh = c;
    }
    __syncthreads();
    double cnt = cntsh;
    double stot = 0.0;
    const float* base = attn + (long long)b * H_ * NTOK * NTOK + LT_ + j;
    for (int h = 0; h < H_; h++) {
        const float* ph = base + (long long)h * NTOK * NTOK;
        double sh = 0.0;
        #pragma unroll 4
        for (int t = 0; t < LT_; t++)
            sh += (double)ph[(long long)t * NTOK] * (double)mf[t];
        stot += sh / cnt;
    }
    S[b * LS_ + j] = (float)(stot / H_);
}

// ---------------- bitonic sort: descending score, ascending index on ties ----------------
__global__ __launch_bounds__(256)
void sort_kernel(const float* __restrict__ S, int* __restrict__ order)
{
    int b = blockIdx.x, t = threadIdx.x;
    __shared__ float val[256];
    __shared__ int   idx[256];
    val[t] = S[b * LS_ + t];
    idx[t] = t;
    __syncthreads();
    for (int k = 2; k <= 256; k <<= 1) {
        for (int j = k >> 1; j > 0; j >>= 1) {
            int p = t ^ j;
            if (p > t) {
                bool desc = ((t & k) == 0);
                float va = val[t], vb = val[p];
                int ia = idx[t], ib = idx[p];
                bool aFirst = (va > vb) || (va == vb && ia < ib);
                if (aFirst != desc) {
                    val[t] = vb; val[p] = va;
                    idx[t] = ib; idx[p] = ia;
                }
            }
            __syncthreads();
        }
    }
    order[b * LS_ + t] = idx[t];
}

// ---------------- gather pruned token rows ----------------
__global__ __launch_bounds__(256)
void gather_kernel(const float* __restrict__ X1, const int* __restrict__ ord,
                   float* __restrict__ X2)
{
    int b = blockIdx.x, t = blockIdx.y;
    int src = (t < LT_) ? t : (LT_ + ord[b * LS_ + (t - LT_)]);
    const float* s = X1 + ((long long)b * NTOK + src) * DIM_;
    float* d = X2 + ((long long)b * N2 + t) * DIM_;
    int i = threadIdx.x;
    d[i] = s[i];
    d[i + 256] = s[i + 256];
    d[i + 512] = s[i + 512];
}

// ---------------- index outputs ----------------
__global__ __launch_bounds__(256)
void indices_kernel(const int* __restrict__ ord, const int* __restrict__ gsi,
                    float* __restrict__ outK, float* __restrict__ outR)
{
    int b = blockIdx.x, t = threadIdx.x;
    if (t < LK_) outK[b * LK_ + t] = (float)gsi[b * LS_ + ord[b * LS_ + t]];
    if (t < LR_) outR[b * LR_ + t] = (float)gsi[b * LS_ + ord[b * LS_ + LK_ + t]];
}

__global__ __launch_bounds__(256)
void git_kernel(const int* __restrict__ git, float* __restrict__ out)
{
    int i = blockIdx.x * 256 + threadIdx.x;
    if (i < B_ * LT_) out[i] = (float)git[i];
}

// ---------------- host orchestration ----------------
static void run_branch(const float* x, const int* gsi, const unsigned char* mask,
                       const float* g1, const float* b1,
                       const float* Wqkv, const float* bqkv,
                       const float* Wproj, const float* bproj,
                       const float* g2, const float* b2,
                       const float* W1, const float* bm1,
                       const float* W2, const float* bm2,
                       float* outX, float* outK, float* outR,
                       float* XLN, float* QKV, float* ATTN, float* O, float* X1,
                       float* S, int* ORD, float* X2, float* XLN2, float* H1m)
{
    // LN1
    ln_kernel<<<B_ * NTOK, 256>>>(x, g1, b1, XLN);

    // QK = XLN @ Wqkv[:, :1536] + bqkv[:1536]  (Kahan: feeds the score ordering)
    gemm_kernel<false, 0, true><<<dim3(2 * DIM_ / BN, B_ * NTOK / BM, 1), 256>>>(
        XLN, DIM_, 0, 0,
        Wqkv, 3 * DIM_, 0, 0,
        QKV, 3 * DIM_, 0, 0,
        bqkv, nullptr, 0, 0, 0,
        DIM_, 1, 1.0f);

    // V = XLN @ Wqkv[:, 1536:] + bqkv[1536:]  (plain fp32: value path only)
    gemm_kernel<false, 0, false><<<dim3(DIM_ / BN, B_ * NTOK / BM, 1), 256>>>(
        XLN, DIM_, 0, 0,
        Wqkv + 2 * DIM_, 3 * DIM_, 0, 0,
        QKV + 2 * DIM_, 3 * DIM_, 0, 0,
        bqkv + 2 * DIM_, nullptr, 0, 0, 0,
        DIM_, 1, 1.0f);

    // scores = q @ k^T * dh^-0.5   per (b,h): [320 x 320, K=64]  (Kahan)
    gemm_kernel<true, 0, true><<<dim3(NTOK / BN, NTOK / BM, B_ * H_), 256>>>(
        QKV,          3 * DIM_, (long long)NTOK * 3 * DIM_, DH,
        QKV + DIM_,   3 * DIM_, (long long)NTOK * 3 * DIM_, DH,
        ATTN, NTOK, (long long)H_ * NTOK * NTOK, (long long)NTOK * NTOK,
        nullptr, nullptr, 0, 0, 0,
        DH, H_, 0.125f);

    softmax_kernel<<<B_ * H_ * NTOK, 128>>>(ATTN);

    // O = P @ V   per (b,h): [320 x 64, K=320], scattered into [B,320,768]
    gemm_kernel<false, 0, false><<<dim3(DH / BN, NTOK / BM, B_ * H_), 256>>>(
        ATTN, NTOK, (long long)H_ * NTOK * NTOK, (long long)NTOK * NTOK,
        QKV + 2 * DIM_, 3 * DIM_, (long long)NTOK * 3 * DIM_, DH,
        O, DIM_, (long long)NTOK * DIM_, DH,
        nullptr, nullptr, 0, 0, 0,
        NTOK, H_, 1.0f);

    // X1 = x + O @ Wproj + bproj
    gemm_kernel<false, 0, false><<<dim3(DIM_ / BN, B_ * NTOK / BM, 1), 256>>>(
        O, DIM_, 0, 0,
        Wproj, DIM_, 0, 0,
        X1, DIM_, 0, 0,
        bproj, x, DIM_, 0, 0,
        DIM_, 1, 1.0f);

    // CE: scores, sort, gather, index outputs
    ce_score_kernel<<<B_, 256>>>(ATTN, mask, S);
    sort_kernel<<<B_, 256>>>(S, ORD);
    gather_kernel<<<dim3(B_, N2), 256>>>(X1, ORD, X2);
    indices_kernel<<<B_, 256>>>(ORD, gsi, outK, outR);

    // LN2
    ln_kernel<<<B_ * N2, 256>>>(X2, g2, b2, XLN2);

    // H1 = gelu(XLN2 @ W1 + bm1)   [7808 x 3072]
    gemm_kernel<false, 1, false><<<dim3(4 * DIM_ / BN, B_ * N2 / BM, 1), 256>>>(
        XLN2, DIM_, 0, 0,
        W1, 4 * DIM_, 0, 0,
        H1m, 4 * DIM_, 0, 0,
        bm1, nullptr, 0, 0, 0,
        DIM_, 1, 1.0f);

    // out = X2 + H1 @ W2 + bm2   [7808 x 768]
    gemm_kernel<false, 0, false><<<dim3(DIM_ / BN, B_ * N2 / BM, 1), 256>>>(
        H1m, 4 * DIM_, 0, 0,
        W2, DIM_, 0, 0,
        outX, DIM_, 0, 0,
        bm2, X2, DIM_, 0, 0,
        4 * DIM_, 1, 1.0f);
}

extern "C" void kernel_launch(void* const* d_in, const int* in_sizes, int n_in,
                              void* d_out, int out_size)
{
    const float* x_rgb  = (const float*)d_in[0];
    const float* x_dte  = (const float*)d_in[1];
    const int*   git    = (const int*)d_in[2];
    const int*   gsi_rgb = (const int*)d_in[3];
    const int*   gsi_dte = (const int*)d_in[4];
    const unsigned char* mask = (const unsigned char*)d_in[5];
    const float* g1    = (const float*)d_in[6];
    const float* b1    = (const float*)d_in[7];
    const float* Wqkv  = (const float*)d_in[8];
    const float* bqkv  = (const float*)d_in[9];
    const float* Wproj = (const float*)d_in[10];
    const float* bproj = (const float*)d_in[11];
    const float* g2    = (const float*)d_in[12];
    const float* b2    = (const float*)d_in[13];
    const float* W1    = (const float*)d_in[14];
    const float* bm1   = (const float*)d_in[15];
    const float* W2    = (const float*)d_in[16];
    const float* bm2   = (const float*)d_in[17];

    float* out = (float*)d_out;

    float *XLN, *QKV, *ATTN, *O, *X1, *S, *X2, *XLN2, *H1m;
    int* ORD;
    cudaGetSymbolAddress((void**)&XLN,  g_XLN);
    cudaGetSymbolAddress((void**)&QKV,  g_QKV);
    cudaGetSymbolAddress((void**)&ATTN, g_ATTN);
    cudaGetSymbolAddress((void**)&O,    g_O);
    cudaGetSymbolAddress((void**)&X1,   g_X1);
    cudaGetSymbolAddress((void**)&S,    g_S);
    cudaGetSymbolAddress((void**)&ORD,  g_ORD);
    cudaGetSymbolAddress((void**)&X2,   g_X2);
    cudaGetSymbolAddress((void**)&XLN2, g_XLN2);
    cudaGetSymbolAddress((void**)&H1m,  g_H1);

    // output layout: x0, x1, git, k0, k1, r0, r1 (all as float32)
    const long long XSZ     = (long long)B_ * N2 * DIM_;   // 5,996,544
    const long long GIT_OFF = 2 * XSZ;                     // 11,993,088
    const long long K0_OFF  = GIT_OFF + (long long)B_ * LT_;
    const long long K1_OFF  = K0_OFF + (long long)B_ * LK_;
    const long long R0_OFF  = K1_OFF + (long long)B_ * LK_;
    const long long R1_OFF  = R0_OFF + (long long)B_ * LR_;

    git_kernel<<<(B_ * LT_ + 255) / 256, 256>>>(git, out + GIT_OFF);

    run_branch(x_rgb, gsi_rgb, mask, g1, b1, Wqkv, bqkv, Wproj, bproj, g2, b2,
               W1, bm1, W2, bm2,
               out, out + K0_OFF, out + R0_OFF,
               XLN, QKV, ATTN, O, X1, S, ORD, X2, XLN2, H1m);

    run_branch(x_dte, gsi_dte, mask, g1, b1, Wqkv, bqkv, Wproj, bproj, g2, b2,
               W1, bm1, W2, bm2,
               out + XSZ, out + K1_OFF, out + R1_OFF,
               XLN, QKV, ATTN, O, X1, S, ORD, X2, XLN2, H1m);
}

// round 3
// speedup vs baseline: 1.2799x; 1.2799x over previous
#include <cuda_runtime.h>
#include <math.h>

// ---------------- problem constants ----------------
#define B_    32
#define LT_   64
#define LS_   256
#define NTOK  320      // LT + LS
#define DIM_  768
#define H_    12
#define DH    64
#define LK_   180
#define LR_   76
#define N2    244      // LT + LK

// ---------------- scratch ----------------
__device__ float g_XLN [B_ * NTOK * DIM_];
__device__ float g_QKV [B_ * NTOK * 3 * DIM_];
__device__ float g_ATTN[(size_t)B_ * H_ * NTOK * NTOK];
__device__ float g_O   [B_ * NTOK * DIM_];
__device__ float g_X1  [B_ * NTOK * DIM_];
__device__ float g_S   [B_ * LS_];
__device__ int   g_ORD [B_ * LS_];
__device__ float g_X2  [B_ * N2 * DIM_];
__device__ float g_XLN2[B_ * N2 * DIM_];
__device__ float g_H1  [B_ * N2 * 4 * DIM_];

// ================= big plain GEMM: 128x128 block, 8x8 microtile =================
#define GBM 128
#define GBN 128
#define GBK 16

template<int ACT>   // 0 = none, 1 = exact GELU
__global__ __launch_bounds__(256)
void gemm128(const float* __restrict__ A, int lda,
             const float* __restrict__ Bm, int ldb,
             float* __restrict__ C, int ldc,
             const float* __restrict__ bias,
             const float* __restrict__ Res, int ldr,
             int K)
{
    __shared__ float As[2][GBK][GBM + 4];
    __shared__ float Bs[2][GBK][GBN + 4];

    int bm = blockIdx.y * GBM;
    int bn = blockIdx.x * GBN;
    int tid = threadIdx.x;
    int tx = tid & 15, ty = tid >> 4;

    float acc[8][8] = {};

    int arow = tid >> 2;          // 0..63 (+64 for second)
    int akq  = (tid & 3) * 4;
    int brow = tid >> 5;          // 0..7  (+8 for second)
    int bnq  = (tid & 31) * 4;

    float4 ra0, ra1, rb0, rb1;
    // preload tile 0
    ra0 = *(const float4*)&A[(long long)(bm + arow)      * lda + akq];
    ra1 = *(const float4*)&A[(long long)(bm + arow + 64) * lda + akq];
    rb0 = *(const float4*)&Bm[(long long)(brow)     * ldb + bn + bnq];
    rb1 = *(const float4*)&Bm[(long long)(brow + 8) * ldb + bn + bnq];
    As[0][akq+0][arow] = ra0.x; As[0][akq+1][arow] = ra0.y;
    As[0][akq+2][arow] = ra0.z; As[0][akq+3][arow] = ra0.w;
    As[0][akq+0][arow+64] = ra1.x; As[0][akq+1][arow+64] = ra1.y;
    As[0][akq+2][arow+64] = ra1.z; As[0][akq+3][arow+64] = ra1.w;
    *(float4*)&Bs[0][brow][bnq]     = rb0;
    *(float4*)&Bs[0][brow + 8][bnq] = rb1;
    __syncthreads();

    int nk = K / GBK;
    for (int kt = 0; kt < nk; kt++) {
        int buf = kt & 1;
        if (kt + 1 < nk) {
            int k0 = (kt + 1) * GBK;
            ra0 = *(const float4*)&A[(long long)(bm + arow)      * lda + k0 + akq];
            ra1 = *(const float4*)&A[(long long)(bm + arow + 64) * lda + k0 + akq];
            rb0 = *(const float4*)&Bm[(long long)(k0 + brow)     * ldb + bn + bnq];
            rb1 = *(const float4*)&Bm[(long long)(k0 + brow + 8) * ldb + bn + bnq];
        }
        #pragma unroll
        for (int kk = 0; kk < GBK; kk++) {
            float af[8], bf[8];
            *(float4*)&af[0] = *(const float4*)&As[buf][kk][ty * 8];
            *(float4*)&af[4] = *(const float4*)&As[buf][kk][ty * 8 + 4];
            *(float4*)&bf[0] = *(const float4*)&Bs[buf][kk][tx * 8];
            *(float4*)&bf[4] = *(const float4*)&Bs[buf][kk][tx * 8 + 4];
            #pragma unroll
            for (int i = 0; i < 8; i++)
                #pragma unroll
                for (int j = 0; j < 8; j++)
                    acc[i][j] = __fmaf_rn(af[i], bf[j], acc[i][j]);
        }
        if (kt + 1 < nk) {
            int nb = buf ^ 1;
            As[nb][akq+0][arow] = ra0.x; As[nb][akq+1][arow] = ra0.y;
            As[nb][akq+2][arow] = ra0.z; As[nb][akq+3][arow] = ra0.w;
            As[nb][akq+0][arow+64] = ra1.x; As[nb][akq+1][arow+64] = ra1.y;
            As[nb][akq+2][arow+64] = ra1.z; As[nb][akq+3][arow+64] = ra1.w;
            *(float4*)&Bs[nb][brow][bnq]     = rb0;
            *(float4*)&Bs[nb][brow + 8][bnq] = rb1;
        }
        __syncthreads();
    }

    #pragma unroll
    for (int i = 0; i < 8; i++) {
        int m = bm + ty * 8 + i;
        float vout[8];
        #pragma unroll
        for (int j = 0; j < 8; j++) {
            int n = bn + tx * 8 + j;
            float v = acc[i][j];
            if (bias) v += bias[n];
            if (Res)  v += Res[(long long)m * ldr + n];
            if (ACT == 1) v = 0.5f * v * (1.0f + erff(v * 0.70710678118654752f));
            vout[j] = v;
        }
        *(float4*)&C[(long long)m * ldc + bn + tx * 8]     = *(float4*)&vout[0];
        *(float4*)&C[(long long)m * ldc + bn + tx * 8 + 4] = *(float4*)&vout[4];
    }
}

// ================= 64x64 GEMM (Kahan-capable, batched) =================
#define BM 64
#define BN 64
#define BK 16

template<bool TRANSB, int ACT, bool KAHAN>
__global__ __launch_bounds__(256)
void gemm_kernel(const float* __restrict__ A, int lda, long long sA1, long long sA2,
                 const float* __restrict__ Bm, int ldb, long long sB1, long long sB2,
                 float* __restrict__ C, int ldc, long long sC1, long long sC2,
                 const float* __restrict__ bias,
                 const float* __restrict__ Res, int ldr, long long sR1, long long sR2,
                 int K, int bdiv, float alpha)
{
    __shared__ float As[BK][BM + 4];
    __shared__ float Bs[BK][BN + 4];

    int bz = blockIdx.z;
    int ob = bz / bdiv;
    int ib = bz - ob * bdiv;
    A  += ob * sA1 + ib * sA2;
    Bm += ob * sB1 + ib * sB2;
    C  += ob * sC1 + ib * sC2;
    if (Res) Res += ob * sR1 + ib * sR2;

    int bm = blockIdx.y * BM;
    int bn = blockIdx.x * BN;
    int tid = threadIdx.x;
    int tx = tid & 15, ty = tid >> 4;

    float acc[4][4] = {};
    float cmp[4][4] = {};

    for (int k0 = 0; k0 < K; k0 += BK) {
        #pragma unroll
        for (int i = 0; i < 4; i++) {
            int idx = tid + i * 256;
            int m  = idx >> 4;
            int kk = idx & 15;
            As[kk][m] = A[(long long)(bm + m) * lda + k0 + kk];
        }
        if (TRANSB) {
            #pragma unroll
            for (int i = 0; i < 4; i++) {
                int idx = tid + i * 256;
                int n  = idx >> 4;
                int kk = idx & 15;
                Bs[kk][n] = Bm[(long long)(bn + n) * ldb + k0 + kk];
            }
        } else {
            #pragma unroll
            for (int i = 0; i < 4; i++) {
                int idx = tid + i * 256;
                int kk = idx >> 6;
                int n  = idx & 63;
                Bs[kk][n] = Bm[(long long)(k0 + kk) * ldb + bn + n];
            }
        }
        __syncthreads();

        #pragma unroll
        for (int kk = 0; kk < BK; kk++) {
            float4 av = *(const float4*)&As[kk][ty * 4];
            float4 bv = *(const float4*)&Bs[kk][tx * 4];
            float a4[4] = {av.x, av.y, av.z, av.w};
            float b4[4] = {bv.x, bv.y, bv.z, bv.w};
            #pragma unroll
            for (int i = 0; i < 4; i++)
                #pragma unroll
                for (int j = 0; j < 4; j++) {
                    if (KAHAN) {
                        float y = __fmaf_rn(a4[i], b4[j], -cmp[i][j]);
                        float t = acc[i][j] + y;
                        cmp[i][j] = (t - acc[i][j]) - y;
                        acc[i][j] = t;
                    } else {
                        acc[i][j] = __fmaf_rn(a4[i], b4[j], acc[i][j]);
                    }
                }
        }
        __syncthreads();
    }

    #pragma unroll
    for (int i = 0; i < 4; i++) {
        int m = bm + ty * 4 + i;
        #pragma unroll
        for (int j = 0; j < 4; j++) {
            int n = bn + tx * 4 + j;
            float v = acc[i][j] * alpha;
            if (bias) v += bias[n];
            if (Res)  v += Res[(long long)m * ldr + n];
            if (ACT == 1) v = 0.5f * v * (1.0f + erff(v * 0.70710678118654752f));
            C[(long long)m * ldc + n] = v;
        }
    }
}

// ---------------- LayerNorm (row = 768), fp64 statistics ----------------
__global__ __launch_bounds__(256)
void ln_kernel(const float* __restrict__ x, const float* __restrict__ g,
               const float* __restrict__ b, float* __restrict__ y)
{
    long long row = blockIdx.x;
    const float* xr = x + row * DIM_;
    float* yr = y + row * DIM_;
    int t = threadIdx.x;
    float v0 = xr[t], v1 = xr[t + 256], v2 = xr[t + 512];
    double s = (double)v0 + (double)v1 + (double)v2;
    double q = (double)v0 * v0 + (double)v1 * v1 + (double)v2 * v2;
    __shared__ double sh[16];
    __shared__ float  par[2];
    #pragma unroll
    for (int o = 16; o > 0; o >>= 1) {
        s += __shfl_down_sync(~0u, s, o);
        q += __shfl_down_sync(~0u, q, o);
    }
    int wid = t >> 5, lane = t & 31;
    if (lane == 0) { sh[wid] = s; sh[wid + 8] = q; }
    __syncthreads();
    if (t == 0) {
        double ss = 0., qq = 0.;
        #pragma unroll
        for (int i = 0; i < 8; i++) { ss += sh[i]; qq += sh[i + 8]; }
        double mu = ss / DIM_;
        double var = qq / DIM_ - mu * mu;
        par[0] = (float)mu;
        par[1] = (float)(1.0 / sqrt(var + 1e-5));
    }
    __syncthreads();
    float mu = par[0], r = par[1];
    yr[t]       = (v0 - mu) * r * g[t]       + b[t];
    yr[t + 256] = (v1 - mu) * r * g[t + 256] + b[t + 256];
    yr[t + 512] = (v2 - mu) * r * g[t + 512] + b[t + 512];
}

// ---------------- row softmax over 320 ----------------
// fp64 path only for score-critical rows (query t < LT), fp32 otherwise.
__global__ __launch_bounds__(128)
void softmax_kernel(float* __restrict__ attn)
{
    long long row = blockIdx.x;
    int t_q = (int)(row % NTOK);
    float* p = attn + row * NTOK;
    int t = threadIdx.x;
    float v[3];
    float m = -1e30f;
    #pragma unroll
    for (int i = 0; i < 3; i++) {
        int c = t + i * 128;
        v[i] = (c < NTOK) ? p[c] : -1e30f;
        m = fmaxf(m, v[i]);
    }
    __shared__ float shm[4];
    __shared__ double shd[4];
    #pragma unroll
    for (int o = 16; o > 0; o >>= 1) m = fmaxf(m, __shfl_xor_sync(~0u, m, o));
    if ((t & 31) == 0) shm[t >> 5] = m;
    __syncthreads();
    m = fmaxf(fmaxf(shm[0], shm[1]), fmaxf(shm[2], shm[3]));
    __syncthreads();

    if (t_q < LT_) {
        // fp64 path — bit-identical to the passing round-2 configuration
        double e[3];
        double s = 0.0;
        #pragma unroll
        for (int i = 0; i < 3; i++) {
            int c = t + i * 128;
            if (c < NTOK) { e[i] = exp((double)v[i] - (double)m); s += e[i]; }
            else e[i] = 0.0;
        }
        #pragma unroll
        for (int o = 16; o > 0; o >>= 1) s += __shfl_xor_sync(~0u, s, o);
        if ((t & 31) == 0) shd[t >> 5] = s;
        __syncthreads();
        s = shd[0] + shd[1] + shd[2] + shd[3];
        double inv = 1.0 / s;
        #pragma unroll
        for (int i = 0; i < 3; i++) {
            int c = t + i * 128;
            if (c < NTOK) p[c] = (float)(e[i] * inv);
        }
    } else {
        float e[3];
        float s = 0.0f;
        #pragma unroll
        for (int i = 0; i < 3; i++) {
            int c = t + i * 128;
            if (c < NTOK) { e[i] = __expf(v[i] - m); s += e[i]; }
            else e[i] = 0.0f;
        }
        #pragma unroll
        for (int o = 16; o > 0; o >>= 1) s += __shfl_xor_sync(~0u, s, o);
        if ((t & 31) == 0) shm[t >> 5] = s;
        __syncthreads();
        s = shm[0] + shm[1] + shm[2] + shm[3];
        float inv = 1.0f / s;
        #pragma unroll
        for (int i = 0; i < 3; i++) {
            int c = t + i * 128;
            if (c < NTOK) p[c] = e[i] * inv;
        }
    }
}

// ---------------- CE scores (fp64 accumulation) ----------------
__global__ __launch_bounds__(256)
void ce_score_kernel(const float* __restrict__ attn, const unsigned char* __restrict__ maskp,
                     float* __restrict__ S)
{
    int b = blockIdx.x;
    int j = threadIdx.x;
    __shared__ float mf[LT_];
    __shared__ double cntsh;
    __shared__ int mode;
    if (j == 0) {
        const unsigned int* w = (const unsigned int*)maskp;
        bool all_int = true, all_flt = true;
        for (int i = 0; i < 512; i++) {
            unsigned int v = w[i];
            if (v != 0u && v != 1u) all_int = false;
            if (v != 0u && v != 0x3F800000u) all_flt = false;
        }
        mode = all_int ? 0 : (all_flt ? 1 : 2);
    }
    __syncthreads();
    if (j < LT_) {
        int mv;
        if (mode == 0)      mv = ((const int*)maskp)[b * LT_ + j] != 0;
        else if (mode == 1) mv = ((const float*)maskp)[b * LT_ + j] != 0.0f;
        else                mv = maskp[b * LT_ + j] != 0;
        mf[j] = mv ? 1.0f : 0.0f;
    }
    __syncthreads();
    if (j == 0) {
        double c = 0.;
        for (int t = 0; t < LT_; t++) c += (double)mf[t];
        cntsh = c;
    }
    __syncthreads();
    double cnt = cntsh;
    double stot = 0.0;
    const float* base = attn + (long long)b * H_ * NTOK * NTOK + LT_ + j;
    for (int h = 0; h < H_; h++) {
        const float* ph = base + (long long)h * NTOK * NTOK;
        double sh = 0.0;
        #pragma unroll 4
        for (int t = 0; t < LT_; t++)
            sh += (double)ph[(long long)t * NTOK] * (double)mf[t];
        stot += sh / cnt;
    }
    S[b * LS_ + j] = (float)(stot / H_);
}

// ---------------- bitonic sort ----------------
__global__ __launch_bounds__(256)
void sort_kernel(const float* __restrict__ S, int* __restrict__ order)
{
    int b = blockIdx.x, t = threadIdx.x;
    __shared__ float val[256];
    __shared__ int   idx[256];
    val[t] = S[b * LS_ + t];
    idx[t] = t;
    __syncthreads();
    for (int k = 2; k <= 256; k <<= 1) {
        for (int j = k >> 1; j > 0; j >>= 1) {
            int p = t ^ j;
            if (p > t) {
                bool desc = ((t & k) == 0);
                float va = val[t], vb = val[p];
                int ia = idx[t], ib = idx[p];
                bool aFirst = (va > vb) || (va == vb && ia < ib);
                if (aFirst != desc) {
                    val[t] = vb; val[p] = va;
                    idx[t] = ib; idx[p] = ia;
                }
            }
            __syncthreads();
        }
    }
    order[b * LS_ + t] = idx[t];
}

// ---------------- gather ----------------
__global__ __launch_bounds__(256)
void gather_kernel(const float* __restrict__ X1, const int* __restrict__ ord,
                   float* __restrict__ X2)
{
    int b = blockIdx.x, t = blockIdx.y;
    int src = (t < LT_) ? t : (LT_ + ord[b * LS_ + (t - LT_)]);
    const float* s = X1 + ((long long)b * NTOK + src) * DIM_;
    float* d = X2 + ((long long)b * N2 + t) * DIM_;
    int i = threadIdx.x;
    d[i] = s[i];
    d[i + 256] = s[i + 256];
    d[i + 512] = s[i + 512];
}

// ---------------- index outputs ----------------
__global__ __launch_bounds__(256)
void indices_kernel(const int* __restrict__ ord, const int* __restrict__ gsi,
                    float* __restrict__ outK, float* __restrict__ outR)
{
    int b = blockIdx.x, t = threadIdx.x;
    if (t < LK_) outK[b * LK_ + t] = (float)gsi[b * LS_ + ord[b * LS_ + t]];
    if (t < LR_) outR[b * LR_ + t] = (float)gsi[b * LS_ + ord[b * LS_ + LK_ + t]];
}

__global__ __launch_bounds__(256)
void git_kernel(const int* __restrict__ git, float* __restrict__ out)
{
    int i = blockIdx.x * 256 + threadIdx.x;
    if (i < B_ * LT_) out[i] = (float)git[i];
}

// ---------------- host orchestration ----------------
static void run_branch(const float* x, const int* gsi, const unsigned char* mask,
                       const float* g1, const float* b1,
                       const float* Wqkv, const float* bqkv,
                       const float* Wproj, const float* bproj,
                       const float* g2, const float* b2,
                       const float* W1, const float* bm1,
                       const float* W2, const float* bm2,
                       float* outX, float* outK, float* outR,
                       float* XLN, float* QKV, float* ATTN, float* O, float* X1,
                       float* S, int* ORD, float* X2, float* XLN2, float* H1m)
{
    // LN1
    ln_kernel<<<B_ * NTOK, 256>>>(x, g1, b1, XLN);

    // Full QKV, fast plain path: [10240 x 2304] = XLN @ Wqkv + bqkv
    gemm128<0><<<dim3(3 * DIM_ / GBN, B_ * NTOK / GBM), 256>>>(
        XLN, DIM_, Wqkv, 3 * DIM_, QKV, 3 * DIM_, bqkv, nullptr, 0, DIM_);

    // Kahan overwrite of score-path pieces (bit-identical to round-2 config):
    // k (all rows): cols [768,1536)
    gemm_kernel<false, 0, true><<<dim3(DIM_ / BN, B_ * NTOK / BM, 1), 256>>>(
        XLN, DIM_, 0, 0,
        Wqkv + DIM_, 3 * DIM_, 0, 0,
        QKV + DIM_, 3 * DIM_, 0, 0,
        bqkv + DIM_, nullptr, 0, 0, 0,
        DIM_, 1, 1.0f);
    // q rows t<64 per batch: cols [0,768)
    gemm_kernel<false, 0, true><<<dim3(DIM_ / BN, 1, B_), 256>>>(
        XLN, DIM_, 0, (long long)NTOK * DIM_,
        Wqkv, 3 * DIM_, 0, 0,
        QKV, 3 * DIM_, 0, (long long)NTOK * 3 * DIM_,
        bqkv, nullptr, 0, 0, 0,
        DIM_, B_, 1.0f);

    // logits rows 0..63 (score-critical): Kahan
    gemm_kernel<true, 0, true><<<dim3(NTOK / BN, 1, B_ * H_), 256>>>(
        QKV,        3 * DIM_, (long long)NTOK * 3 * DIM_, DH,
        QKV + DIM_, 3 * DIM_, (long long)NTOK * 3 * DIM_, DH,
        ATTN, NTOK, (long long)H_ * NTOK * NTOK, (long long)NTOK * NTOK,
        nullptr, nullptr, 0, 0, 0,
        DH, H_, 0.125f);
    // logits rows 64..319: plain
    gemm_kernel<true, 0, false><<<dim3(NTOK / BN, 4, B_ * H_), 256>>>(
        QKV + (long long)LT_ * 3 * DIM_, 3 * DIM_, (long long)NTOK * 3 * DIM_, DH,
        QKV + DIM_,                      3 * DIM_, (long long)NTOK * 3 * DIM_, DH,
        ATTN + (long long)LT_ * NTOK, NTOK, (long long)H_ * NTOK * NTOK, (long long)NTOK * NTOK,
        nullptr, nullptr, 0, 0, 0,
        DH, H_, 0.125f);

    softmax_kernel<<<B_ * H_ * NTOK, 128>>>(ATTN);

    // O = P @ V   per (b,h): [320 x 64, K=320]
    gemm_kernel<false, 0, false><<<dim3(DH / BN, NTOK / BM, B_ * H_), 256>>>(
        ATTN, NTOK, (long long)H_ * NTOK * NTOK, (long long)NTOK * NTOK,
        QKV + 2 * DIM_, 3 * DIM_, (long long)NTOK * 3 * DIM_, DH,
        O, DIM_, (long long)NTOK * DIM_, DH,
        nullptr, nullptr, 0, 0, 0,
        NTOK, H_, 1.0f);

    // X1 = x + O @ Wproj + bproj
    gemm128<0><<<dim3(DIM_ / GBN, B_ * NTOK / GBM), 256>>>(
        O, DIM_, Wproj, DIM_, X1, DIM_, bproj, x, DIM_, DIM_);

    // CE
    ce_score_kernel<<<B_, 256>>>(ATTN, mask, S);
    sort_kernel<<<B_, 256>>>(S, ORD);
    gather_kernel<<<dim3(B_, N2), 256>>>(X1, ORD, X2);
    indices_kernel<<<B_, 256>>>(ORD, gsi, outK, outR);

    // LN2
    ln_kernel<<<B_ * N2, 256>>>(X2, g2, b2, XLN2);

    // H1 = gelu(XLN2 @ W1 + bm1)   [7808 x 3072]
    gemm128<1><<<dim3(4 * DIM_ / GBN, B_ * N2 / GBM), 256>>>(
        XLN2, DIM_, W1, 4 * DIM_, H1m, 4 * DIM_, bm1, nullptr, 0, DIM_);

    // out = X2 + H1 @ W2 + bm2   [7808 x 768]
    gemm128<0><<<dim3(DIM_ / GBN, B_ * N2 / GBM), 256>>>(
        H1m, 4 * DIM_, W2, DIM_, outX, DIM_, bm2, X2, DIM_, 4 * DIM_);
}

extern "C" void kernel_launch(void* const* d_in, const int* in_sizes, int n_in,
                              void* d_out, int out_size)
{
    const float* x_rgb  = (const float*)d_in[0];
    const float* x_dte  = (const float*)d_in[1];
    const int*   git    = (const int*)d_in[2];
    const int*   gsi_rgb = (const int*)d_in[3];
    const int*   gsi_dte = (const int*)d_in[4];
    const unsigned char* mask = (const unsigned char*)d_in[5];
    const float* g1    = (const float*)d_in[6];
    const float* b1    = (const float*)d_in[7];
    const float* Wqkv  = (const float*)d_in[8];
    const float* bqkv  = (const float*)d_in[9];
    const float* Wproj = (const float*)d_in[10];
    const float* bproj = (const float*)d_in[11];
    const float* g2    = (const float*)d_in[12];
    const float* b2    = (const float*)d_in[13];
    const float* W1    = (const float*)d_in[14];
    const float* bm1   = (const float*)d_in[15];
    const float* W2    = (const float*)d_in[16];
    const float* bm2   = (const float*)d_in[17];

    float* out = (float*)d_out;

    float *XLN, *QKV, *ATTN, *O, *X1, *S, *X2, *XLN2, *H1m;
    int* ORD;
    cudaGetSymbolAddress((void**)&XLN,  g_XLN);
    cudaGetSymbolAddress((void**)&QKV,  g_QKV);
    cudaGetSymbolAddress((void**)&ATTN, g_ATTN);
    cudaGetSymbolAddress((void**)&O,    g_O);
    cudaGetSymbolAddress((void**)&X1,   g_X1);
    cudaGetSymbolAddress((void**)&S,    g_S);
    cudaGetSymbolAddress((void**)&ORD,  g_ORD);
    cudaGetSymbolAddress((void**)&X2,   g_X2);
    cudaGetSymbolAddress((void**)&XLN2, g_XLN2);
    cudaGetSymbolAddress((void**)&H1m,  g_H1);

    const long long XSZ     = (long long)B_ * N2 * DIM_;
    const long long GIT_OFF = 2 * XSZ;
    const long long K0_OFF  = GIT_OFF + (long long)B_ * LT_;
    const long long K1_OFF  = K0_OFF + (long long)B_ * LK_;
    const long long R0_OFF  = K1_OFF + (long long)B_ * LK_;
    const long long R1_OFF  = R0_OFF + (long long)B_ * LR_;

    git_kernel<<<(B_ * LT_ + 255) / 256, 256>>>(git, out + GIT_OFF);

    run_branch(x_rgb, gsi_rgb, mask, g1, b1, Wqkv, bqkv, Wproj, bproj, g2, b2,
               W1, bm1, W2, bm2,
               out, out + K0_OFF, out + R0_OFF,
               XLN, QKV, ATTN, O, X1, S, ORD, X2, XLN2, H1m);

    run_branch(x_dte, gsi_dte, mask, g1, b1, Wqkv, bqkv, Wproj, bproj, g2, b2,
               W1, bm1, W2, bm2,
               out + XSZ, out + K1_OFF, out + R1_OFF,
               XLN, QKV, ATTN, O, X1, S, ORD, X2, XLN2, H1m);
}

// round 5
// speedup vs baseline: 1.9059x; 1.4891x over previous
#include <cuda_runtime.h>
#include <cuda_bf16.h>
#include <math.h>
#include <stdint.h>

// ---------------- problem constants ----------------
#define B_    32
#define LT_   64
#define LS_   256
#define NTOK  320      // LT + LS
#define DIM_  768
#define H_    12
#define DH    64
#define LK_   180
#define LR_   76
#define N2    244      // LT + LK

// arch gate: tcgen05 only exists in the sm_103a-specific pass
#if defined(__CUDA_ARCH__) && defined(__CUDA_ARCH_FEAT_SM103_ALL)
#define HAS_TCGEN05 1
#else
#define HAS_TCGEN05 0
#endif

// ---------------- scratch ----------------
__device__ float g_XLN [B_ * NTOK * DIM_];
__device__ float g_QKV [B_ * NTOK * 3 * DIM_];
__device__ float g_ATTN[(size_t)B_ * H_ * NTOK * NTOK];
__device__ float g_O   [B_ * NTOK * DIM_];
__device__ float g_X1  [B_ * NTOK * DIM_];
__device__ float g_S   [B_ * LS_];
__device__ int   g_ORD [B_ * LS_];
__device__ float g_X2  [B_ * N2 * DIM_];
__device__ float g_XLN2[B_ * N2 * DIM_];
__device__ float g_H1  [B_ * N2 * 4 * DIM_];

// =====================================================================
// tcgen05 helpers (sm_103a pass only)
// =====================================================================
#if HAS_TCGEN05
__device__ __forceinline__ uint32_t elect_one_pred() {
    uint32_t pred;
    asm volatile(
        "{\n\t.reg .pred p;\n\telect.sync _|p, 0xFFFFFFFF;\n\tselp.b32 %0, 1, 0, p;\n\t}"
        : "=r"(pred));
    return pred;
}
__device__ __forceinline__ uint32_t smem_to_u32(const void* smem_ptr) {
    uint32_t addr;
    asm("{ .reg .u64 tmp; cvta.to.shared.u64 tmp, %1; cvt.u32.u64 %0, tmp; }"
        : "=r"(addr) : "l"(smem_ptr));
    return addr;
}

#define TCGEN05_ALLOC(smem_result_addr, nCols) \
    asm volatile("tcgen05.alloc.cta_group::1.sync.aligned.shared::cta.b32 [%0], %1;" \
        :: "r"((uint32_t)(smem_result_addr)), "r"((uint32_t)(nCols)) : "memory")
#define TCGEN05_DEALLOC(tmem_addr, nCols) \
    asm volatile("tcgen05.dealloc.cta_group::1.sync.aligned.b32 %0, %1;" \
        :: "r"(tmem_addr), "r"((uint32_t)(nCols)))
#define TCGEN05_RELINQUISH_ALLOC_PERMIT() \
    asm volatile("tcgen05.relinquish_alloc_permit.cta_group::1.sync.aligned;")
#define TCGEN05_COMMIT(mbar_smem_addr) \
    asm volatile("tcgen05.commit.cta_group::1.mbarrier::arrive::one.shared::cluster.b64 [%0];" \
        :: "r"((uint32_t)(mbar_smem_addr)) : "memory")
#define TCGEN05_WAIT_LD() \
    asm volatile("tcgen05.wait::ld.sync.aligned;" ::: "memory")
#define TCGEN05_FENCE_BEFORE() \
    asm volatile("tcgen05.fence::before_thread_sync;" ::: "memory")
#define TCGEN05_FENCE_AFTER() \
    asm volatile("tcgen05.fence::after_thread_sync;" ::: "memory")
#define FENCE_PROXY_ASYNC_SHARED_CTA() \
    asm volatile("fence.proxy.async.shared::cta;" ::: "memory")
#define MBARRIER_INIT(mbar_smem_addr, count) \
    asm volatile("mbarrier.init.shared.b64 [%0], %1;" \
        :: "r"((uint32_t)(mbar_smem_addr)), "r"((uint32_t)(count)) : "memory")
#define MBARRIER_INVAL(mbar_smem_addr) \
    asm volatile("mbarrier.inval.shared.b64 [%0];" \
        :: "r"((uint32_t)(mbar_smem_addr)) : "memory")

#define MBARRIER_WAIT_PARITY(mbar_smem_addr, phase_parity) do { \
    uint32_t _mbar = (uint32_t)(mbar_smem_addr); \
    uint32_t _parity = (uint32_t)(phase_parity); \
    uint32_t _done; \
    asm volatile( \
        "{\n\t.reg .pred p;\n\t" \
        "mbarrier.try_wait.parity.acquire.cta.shared::cta.b64 p, [%1], %2;\n\t" \
        "selp.b32 %0, 1, 0, p;\n\t}" \
        : "=r"(_done) : "r"(_mbar), "r"(_parity) : "memory"); \
    if (!_done) { \
        asm volatile( \
            "{\n\t.reg .pred P1;\n\t" \
            "WAIT_LOOP_%=:\n\t" \
            "mbarrier.try_wait.parity.acquire.cta.shared::cta.b64 P1, [%0], %1, 0x989680;\n\t" \
            "@P1 bra.uni WAIT_DONE_%=;\n\t" \
            "bra.uni WAIT_LOOP_%=;\n\t" \
            "WAIT_DONE_%=:\n\t}" \
            :: "r"(_mbar), "r"(_parity) : "memory"); \
    } \
} while(0)

#define TCGEN05_LD_32X32B_X32(r, tmem_addr) \
    asm volatile( \
        "tcgen05.ld.sync.aligned.32x32b.x32.b32 " \
        "{%0, %1, %2, %3, %4, %5, %6, %7, " \
        " %8, %9, %10, %11, %12, %13, %14, %15, " \
        " %16, %17, %18, %19, %20, %21, %22, %23, " \
        " %24, %25, %26, %27, %28, %29, %30, %31}, [%32];" \
        : "=r"((r)[0]),  "=r"((r)[1]),  "=r"((r)[2]),  "=r"((r)[3]), \
          "=r"((r)[4]),  "=r"((r)[5]),  "=r"((r)[6]),  "=r"((r)[7]), \
          "=r"((r)[8]),  "=r"((r)[9]),  "=r"((r)[10]), "=r"((r)[11]), \
          "=r"((r)[12]), "=r"((r)[13]), "=r"((r)[14]), "=r"((r)[15]), \
          "=r"((r)[16]), "=r"((r)[17]), "=r"((r)[18]), "=r"((r)[19]), \
          "=r"((r)[20]), "=r"((r)[21]), "=r"((r)[22]), "=r"((r)[23]), \
          "=r"((r)[24]), "=r"((r)[25]), "=r"((r)[26]), "=r"((r)[27]), \
          "=r"((r)[28]), "=r"((r)[29]), "=r"((r)[30]), "=r"((r)[31]) \
        : "r"(tmem_addr))

static constexpr uint64_t SMEM_DESC_BASE_SW128 =
    (uint64_t(2)  << 61) | (uint64_t(1) << 46) | (uint64_t(64) << 32) | (uint64_t(1) << 16);
#define MAKE_SMEM_DESC(base_addr) \
    (SMEM_DESC_BASE_SW128 | ((uint64_t)((base_addr) >> 4) & 0x3FFF))

__device__ __forceinline__ void tc_mma_f16_ss(uint32_t d, uint64_t a, uint64_t b,
                                              uint32_t idesc, uint32_t en)
{
    asm volatile(
        "{\n\t.reg .pred p;\n\tsetp.ne.u32 p, %5, 0;\n\t"
        "tcgen05.mma.cta_group::1.kind::f16 [%0], %1, %2, %3, {%4, %4, %4, %4}, p;\n\t}"
        :: "r"(d), "l"(a), "l"(b), "r"(idesc), "r"(0u), "r"(en) : "memory");
}
#endif // HAS_TCGEN05

// =====================================================================
// Tensor-core GEMM: C[M,N] = act(A[M,K] @ B[K,N] + bias + Res)
// bf16 2-way split (hi/lo), 3 MMAs per tile chunk: hh + hl + lh.
// Tile 128x128, BK=64, double-buffered SMEM. M,N %128==0, K %128==0.
// Non-sm_103a PTX pass gets a correct fp32 fallback body.
// =====================================================================
#define TC_THREADS 256
#define TC_SMEM_TOTAL (1024 + 2 * 4 * 16384)   // 132096 bytes
#define TC_IDESC 0x8200490u   // F32 accum, bf16 x bf16, N=128, M=128

template<int ACT>   // 0 = none, 1 = exact GELU
__global__ __launch_bounds__(TC_THREADS)
void tc_gemm(const float* __restrict__ A, int lda,
             const float* __restrict__ Bm, int ldb,
             float* __restrict__ C, int ldc,
             const float* __restrict__ bias,
             const float* __restrict__ Res, int ldr,
             int K)
{
#if HAS_TCGEN05
    extern __shared__ char smem[];
    const uint32_t sb = smem_to_u32(smem);
    const int tid = threadIdx.x;
    const int wid = tid >> 5;
    const int lid = tid & 31;
    const int m0 = blockIdx.y * 128;
    const int n0 = blockIdx.x * 128;

    if (wid == 0) {
        TCGEN05_ALLOC(sb + 0, 128);
        TCGEN05_RELINQUISH_ALLOC_PERMIT();
    }
    if (tid == 0) {
        MBARRIER_INIT(sb + 16, 1);
        MBARRIER_INIT(sb + 24, 1);
    }
    __syncthreads();
    uint32_t tmem;
    asm volatile("ld.shared.b32 %0, [%1];" : "=r"(tmem) : "r"(sb));

    const int nk = K >> 6;   // chunks of 64

    for (int kt = 0; kt < nk; kt++) {
        const int buf = kt & 1;
        char* base = smem + 1024 + buf * 65536;
        if (kt >= 2) {
            MBARRIER_WAIT_PARITY(sb + 16 + 8 * ((kt - 2) & 1), ((kt - 2) >> 1) & 1);
        }
        // ---- load + split A chunk ----
        {
            const float* Ag = A + (long long)m0 * lda + kt * 64;
            #pragma unroll
            for (int i = 0; i < 8; i++) {
                int idx = tid + i * 256;
                int r  = idx >> 4;
                int cq = (idx & 15) * 4;
                float4 v = *(const float4*)&Ag[(long long)r * lda + cq];
                float xs[4] = {v.x, v.y, v.z, v.w};
                unsigned short h[4], l[4];
                #pragma unroll
                for (int j = 0; j < 4; j++) {
                    __nv_bfloat16 hb = __float2bfloat16(xs[j]);
                    float rres = xs[j] - __bfloat162float(hb);
                    __nv_bfloat16 lb = __float2bfloat16(rres);
                    h[j] = __bfloat16_as_ushort(hb);
                    l[j] = __bfloat16_as_ushort(lb);
                }
                uint2 hw = make_uint2((uint32_t)h[0] | ((uint32_t)h[1] << 16),
                                      (uint32_t)h[2] | ((uint32_t)h[3] << 16));
                uint2 lw = make_uint2((uint32_t)l[0] | ((uint32_t)l[1] << 16),
                                      (uint32_t)l[2] | ((uint32_t)l[3] << 16));
                uint32_t bo = r * 128 + cq * 2;
                uint32_t so = bo ^ ((bo >> 3) & 0x70);
                *(uint2*)(base + so)         = hw;
                *(uint2*)(base + 16384 + so) = lw;
            }
        }
        // ---- load + split + transpose B chunk ----
        {
            const float* Bg = Bm + (long long)(kt * 64) * ldb + n0;
            char* bbase = base + 32768;
            #pragma unroll
            for (int i = 0; i < 8; i++) {
                int idx = tid + i * 256;
                int n  = idx & 127;
                int kq = (idx >> 7) * 4;
                float xs[4];
                #pragma unroll
                for (int j = 0; j < 4; j++)
                    xs[j] = Bg[(long long)(kq + j) * ldb + n];
                unsigned short h[4], l[4];
                #pragma unroll
                for (int j = 0; j < 4; j++) {
                    __nv_bfloat16 hb = __float2bfloat16(xs[j]);
                    float rres = xs[j] - __bfloat162float(hb);
                    __nv_bfloat16 lb = __float2bfloat16(rres);
                    h[j] = __bfloat16_as_ushort(hb);
                    l[j] = __bfloat16_as_ushort(lb);
                }
                uint2 hw = make_uint2((uint32_t)h[0] | ((uint32_t)h[1] << 16),
                                      (uint32_t)h[2] | ((uint32_t)h[3] << 16));
                uint2 lw = make_uint2((uint32_t)l[0] | ((uint32_t)l[1] << 16),
                                      (uint32_t)l[2] | ((uint32_t)l[3] << 16));
                uint32_t bo = n * 128 + kq * 2;
                uint32_t so = bo ^ ((bo >> 3) & 0x70);
                *(uint2*)(bbase + so)         = hw;
                *(uint2*)(bbase + 16384 + so) = lw;
            }
        }
        FENCE_PROXY_ASYNC_SHARED_CTA();
        __syncthreads();

        if (wid == 0) {
            if (elect_one_pred()) {
                uint32_t ab = sb + 1024 + buf * 65536;
                uint64_t dAh = MAKE_SMEM_DESC(ab);
                uint64_t dAl = MAKE_SMEM_DESC(ab + 16384);
                uint64_t dBh = MAKE_SMEM_DESC(ab + 32768);
                uint64_t dBl = MAKE_SMEM_DESC(ab + 49152);
                #pragma unroll
                for (int k = 0; k < 4; k++)
                    tc_mma_f16_ss(tmem, dAh + k * 2, dBh + k * 2, TC_IDESC,
                                  (kt == 0 && k == 0) ? 0u : 1u);
                #pragma unroll
                for (int k = 0; k < 4; k++)
                    tc_mma_f16_ss(tmem, dAh + k * 2, dBl + k * 2, TC_IDESC, 1u);
                #pragma unroll
                for (int k = 0; k < 4; k++)
                    tc_mma_f16_ss(tmem, dAl + k * 2, dBh + k * 2, TC_IDESC, 1u);
                TCGEN05_COMMIT(sb + 16 + 8 * buf);
            }
        }
    }

    MBARRIER_WAIT_PARITY(sb + 16 + 8 * ((nk - 2) & 1), ((nk - 2) >> 1) & 1);
    MBARRIER_WAIT_PARITY(sb + 16 + 8 * ((nk - 1) & 1), ((nk - 1) >> 1) & 1);
    TCGEN05_FENCE_AFTER();

    if (wid < 4) {
        int m = m0 + wid * 32 + lid;
        float* Crow = C + (long long)m * ldc + n0;
        const float* Rrow = Res ? (Res + (long long)m * ldr + n0) : (const float*)0;
        #pragma unroll
        for (int cb = 0; cb < 128; cb += 32) {
            uint32_t d[32];
            TCGEN05_LD_32X32B_X32(d, tmem + cb);
            TCGEN05_WAIT_LD();
            float vout[32];
            #pragma unroll
            for (int j = 0; j < 32; j++) {
                float v = __uint_as_float(d[j]);
                if (bias) v += bias[n0 + cb + j];
                if (Rrow) v += Rrow[cb + j];
                if (ACT == 1) v = 0.5f * v * (1.0f + erff(v * 0.70710678118654752f));
                vout[j] = v;
            }
            #pragma unroll
            for (int q = 0; q < 32; q += 4)
                *(float4*)&Crow[cb + q] = *(float4*)&vout[q];
        }
        TCGEN05_FENCE_BEFORE();
    }
    __syncthreads();
    if (tid == 0) { MBARRIER_INVAL(sb + 16); MBARRIER_INVAL(sb + 24); }
    __syncthreads();
    if (wid == 0) TCGEN05_DEALLOC(tmem, 128);

#else
    // -------- fp32 fallback (compute_103 PTX pass; never runs on GB300 when
    // the sm_103a cubin is present, but must be correct) --------
    extern __shared__ char smem[];
    float* As = (float*)smem;                       // [16][132]
    float* Bs = (float*)(smem + 16 * 132 * 4);      // [16][132]
    const int tid = threadIdx.x;
    const int tx = tid & 15, ty = tid >> 4;
    const int m0 = blockIdx.y * 128;
    const int n0 = blockIdx.x * 128;
    float acc[8][8] = {};
    for (int k0 = 0; k0 < K; k0 += 16) {
        #pragma unroll
        for (int i = 0; i < 8; i++) {
            int idx = tid + i * 256;
            int r  = idx >> 4;        // 0..127
            int kk = idx & 15;
            As[kk * 132 + r] = A[(long long)(m0 + r) * lda + k0 + kk];
        }
        #pragma unroll
        for (int i = 0; i < 8; i++) {
            int idx = tid + i * 256;
            int kk = idx >> 7;        // 0..15
            int n  = idx & 127;
            Bs[kk * 132 + n] = Bm[(long long)(k0 + kk) * ldb + n0 + n];
        }
        __syncthreads();
        #pragma unroll
        for (int kk = 0; kk < 16; kk++) {
            float af[8], bf[8];
            #pragma unroll
            for (int i = 0; i < 8; i++) af[i] = As[kk * 132 + ty * 8 + i];
            #pragma unroll
            for (int j = 0; j < 8; j++) bf[j] = Bs[kk * 132 + tx * 8 + j];
            #pragma unroll
            for (int i = 0; i < 8; i++)
                #pragma unroll
                for (int j = 0; j < 8; j++)
                    acc[i][j] = __fmaf_rn(af[i], bf[j], acc[i][j]);
        }
        __syncthreads();
    }
    #pragma unroll
    for (int i = 0; i < 8; i++) {
        int m = m0 + ty * 8 + i;
        #pragma unroll
        for (int j = 0; j < 8; j++) {
            int n = n0 + tx * 8 + j;
            float v = acc[i][j];
            if (bias) v += bias[n];
            if (Res)  v += Res[(long long)m * ldr + n];
            if (ACT == 1) v = 0.5f * v * (1.0f + erff(v * 0.70710678118654752f));
            C[(long long)m * ldc + n] = v;
        }
    }
#endif
}

// ================= 64x64 GEMM (Kahan-capable, batched) =================
#define BM 64
#define BN 64
#define BK 16

template<bool TRANSB, int ACT, bool KAHAN>
__global__ __launch_bounds__(256)
void gemm_kernel(const float* __restrict__ A, int lda, long long sA1, long long sA2,
                 const float* __restrict__ Bm, int ldb, long long sB1, long long sB2,
                 float* __restrict__ C, int ldc, long long sC1, long long sC2,
                 const float* __restrict__ bias,
                 const float* __restrict__ Res, int ldr, long long sR1, long long sR2,
                 int K, int bdiv, float alpha)
{
    __shared__ float As[BK][BM + 4];
    __shared__ float Bs[BK][BN + 4];

    int bz = blockIdx.z;
    int ob = bz / bdiv;
    int ib = bz - ob * bdiv;
    A  += ob * sA1 + ib * sA2;
    Bm += ob * sB1 + ib * sB2;
    C  += ob * sC1 + ib * sC2;
    if (Res) Res += ob * sR1 + ib * sR2;

    int bm = blockIdx.y * BM;
    int bn = blockIdx.x * BN;
    int tid = threadIdx.x;
    int tx = tid & 15, ty = tid >> 4;

    float acc[4][4] = {};
    float cmp[4][4] = {};

    for (int k0 = 0; k0 < K; k0 += BK) {
        #pragma unroll
        for (int i = 0; i < 4; i++) {
            int idx = tid + i * 256;
            int m  = idx >> 4;
            int kk = idx & 15;
            As[kk][m] = A[(long long)(bm + m) * lda + k0 + kk];
        }
        if (TRANSB) {
            #pragma unroll
            for (int i = 0; i < 4; i++) {
                int idx = tid + i * 256;
                int n  = idx >> 4;
                int kk = idx & 15;
                Bs[kk][n] = Bm[(long long)(bn + n) * ldb + k0 + kk];
            }
        } else {
            #pragma unroll
            for (int i = 0; i < 4; i++) {
                int idx = tid + i * 256;
                int kk = idx >> 6;
                int n  = idx & 63;
                Bs[kk][n] = Bm[(long long)(k0 + kk) * ldb + bn + n];
            }
        }
        __syncthreads();

        #pragma unroll
        for (int kk = 0; kk < BK; kk++) {
            float4 av = *(const float4*)&As[kk][ty * 4];
            float4 bv = *(const float4*)&Bs[kk][tx * 4];
            float a4[4] = {av.x, av.y, av.z, av.w};
            float b4[4] = {bv.x, bv.y, bv.z, bv.w};
            #pragma unroll
            for (int i = 0; i < 4; i++)
                #pragma unroll
                for (int j = 0; j < 4; j++) {
                    if (KAHAN) {
                        float y = __fmaf_rn(a4[i], b4[j], -cmp[i][j]);
                        float t = acc[i][j] + y;
                        cmp[i][j] = (t - acc[i][j]) - y;
                        acc[i][j] = t;
                    } else {
                        acc[i][j] = __fmaf_rn(a4[i], b4[j], acc[i][j]);
                    }
                }
        }
        __syncthreads();
    }

    #pragma unroll
    for (int i = 0; i < 4; i++) {
        int m = bm + ty * 4 + i;
        #pragma unroll
        for (int j = 0; j < 4; j++) {
            int n = bn + tx * 4 + j;
            float v = acc[i][j] * alpha;
            if (bias) v += bias[n];
            if (Res)  v += Res[(long long)m * ldr + n];
            if (ACT == 1) v = 0.5f * v * (1.0f + erff(v * 0.70710678118654752f));
            C[(long long)m * ldc + n] = v;
        }
    }
}

// ---------------- LayerNorm (row = 768), fp64 statistics ----------------
__global__ __launch_bounds__(256)
void ln_kernel(const float* __restrict__ x, const float* __restrict__ g,
               const float* __restrict__ b, float* __restrict__ y)
{
    long long row = blockIdx.x;
    const float* xr = x + row * DIM_;
    float* yr = y + row * DIM_;
    int t = threadIdx.x;
    float v0 = xr[t], v1 = xr[t + 256], v2 = xr[t + 512];
    double s = (double)v0 + (double)v1 + (double)v2;
    double q = (double)v0 * v0 + (double)v1 * v1 + (double)v2 * v2;
    __shared__ double sh[16];
    __shared__ float  par[2];
    #pragma unroll
    for (int o = 16; o > 0; o >>= 1) {
        s += __shfl_down_sync(~0u, s, o);
        q += __shfl_down_sync(~0u, q, o);
    }
    int wid = t >> 5, lane = t & 31;
    if (lane == 0) { sh[wid] = s; sh[wid + 8] = q; }
    __syncthreads();
    if (t == 0) {
        double ss = 0., qq = 0.;
        #pragma unroll
        for (int i = 0; i < 8; i++) { ss += sh[i]; qq += sh[i + 8]; }
        double mu = ss / DIM_;
        double var = qq / DIM_ - mu * mu;
        par[0] = (float)mu;
        par[1] = (float)(1.0 / sqrt(var + 1e-5));
    }
    __syncthreads();
    float mu = par[0], r = par[1];
    yr[t]       = (v0 - mu) * r * g[t]       + b[t];
    yr[t + 256] = (v1 - mu) * r * g[t + 256] + b[t + 256];
    yr[t + 512] = (v2 - mu) * r * g[t + 512] + b[t + 512];
}

// ---------------- row softmax over 320 ----------------
__global__ __launch_bounds__(128)
void softmax_kernel(float* __restrict__ attn)
{
    long long row = blockIdx.x;
    int t_q = (int)(row % NTOK);
    float* p = attn + row * NTOK;
    int t = threadIdx.x;
    float v[3];
    float m = -1e30f;
    #pragma unroll
    for (int i = 0; i < 3; i++) {
        int c = t + i * 128;
        v[i] = (c < NTOK) ? p[c] : -1e30f;
        m = fmaxf(m, v[i]);
    }
    __shared__ float shm[4];
    __shared__ double shd[4];
    #pragma unroll
    for (int o = 16; o > 0; o >>= 1) m = fmaxf(m, __shfl_xor_sync(~0u, m, o));
    if ((t & 31) == 0) shm[t >> 5] = m;
    __syncthreads();
    m = fmaxf(fmaxf(shm[0], shm[1]), fmaxf(shm[2], shm[3]));
    __syncthreads();

    if (t_q < LT_) {
        double e[3];
        double s = 0.0;
        #pragma unroll
        for (int i = 0; i < 3; i++) {
            int c = t + i * 128;
            if (c < NTOK) { e[i] = exp((double)v[i] - (double)m); s += e[i]; }
            else e[i] = 0.0;
        }
        #pragma unroll
        for (int o = 16; o > 0; o >>= 1) s += __shfl_xor_sync(~0u, s, o);
        if ((t & 31) == 0) shd[t >> 5] = s;
        __syncthreads();
        s = shd[0] + shd[1] + shd[2] + shd[3];
        double inv = 1.0 / s;
        #pragma unroll
        for (int i = 0; i < 3; i++) {
            int c = t + i * 128;
            if (c < NTOK) p[c] = (float)(e[i] * inv);
        }
    } else {
        float e[3];
        float s = 0.0f;
        #pragma unroll
        for (int i = 0; i < 3; i++) {
            int c = t + i * 128;
            if (c < NTOK) { e[i] = __expf(v[i] - m); s += e[i]; }
            else e[i] = 0.0f;
        }
        #pragma unroll
        for (int o = 16; o > 0; o >>= 1) s += __shfl_xor_sync(~0u, s, o);
        if ((t & 31) == 0) shm[t >> 5] = s;
        __syncthreads();
        s = shm[0] + shm[1] + shm[2] + shm[3];
        float inv = 1.0f / s;
        #pragma unroll
        for (int i = 0; i < 3; i++) {
            int c = t + i * 128;
            if (c < NTOK) p[c] = e[i] * inv;
        }
    }
}

// ---------------- CE scores (fp64 accumulation) ----------------
__global__ __launch_bounds__(256)
void ce_score_kernel(const float* __restrict__ attn, const unsigned char* __restrict__ maskp,
                     float* __restrict__ S)
{
    int b = blockIdx.x;
    int j = threadIdx.x;
    __shared__ float mf[LT_];
    __shared__ double cntsh;
    __shared__ int mode;
    if (j == 0) {
        const unsigned int* w = (const unsigned int*)maskp;
        bool all_int = true, all_flt = true;
        for (int i = 0; i < 512; i++) {
            unsigned int v = w[i];
            if (v != 0u && v != 1u) all_int = false;
            if (v != 0u && v != 0x3F800000u) all_flt = false;
        }
        mode = all_int ? 0 : (all_flt ? 1 : 2);
    }
    __syncthreads();
    if (j < LT_) {
        int mv;
        if (mode == 0)      mv = ((const int*)maskp)[b * LT_ + j] != 0;
        else if (mode == 1) mv = ((const float*)maskp)[b * LT_ + j] != 0.0f;
        else                mv = maskp[b * LT_ + j] != 0;
        mf[j] = mv ? 1.0f : 0.0f;
    }
    __syncthreads();
    if (j == 0) {
        double c = 0.;
        for (int t = 0; t < LT_; t++) c += (double)mf[t];
        cntsh = c;
    }
    __syncthreads();
    double cnt = cntsh;
    double stot = 0.0;
    const float* base = attn + (long long)b * H_ * NTOK * NTOK + LT_ + j;
    for (int h = 0; h < H_; h++) {
        const float* ph = base + (long long)h * NTOK * NTOK;
        double sh = 0.0;
        #pragma unroll 4
        for (int t = 0; t < LT_; t++)
            sh += (double)ph[(long long)t * NTOK] * (double)mf[t];
        stot += sh / cnt;
    }
    S[b * LS_ + j] = (float)(stot / H_);
}

// ---------------- bitonic sort ----------------
__global__ __launch_bounds__(256)
void sort_kernel(const float* __restrict__ S, int* __restrict__ order)
{
    int b = blockIdx.x, t = threadIdx.x;
    __shared__ float val[256];
    __shared__ int   idx[256];
    val[t] = S[b * LS_ + t];
    idx[t] = t;
    __syncthreads();
    for (int k = 2; k <= 256; k <<= 1) {
        for (int j = k >> 1; j > 0; j >>= 1) {
            int p = t ^ j;
            if (p > t) {
                bool desc = ((t & k) == 0);
                float va = val[t], vb = val[p];
                int ia = idx[t], ib = idx[p];
                bool aFirst = (va > vb) || (va == vb && ia < ib);
                if (aFirst != desc) {
                    val[t] = vb; val[p] = va;
                    idx[t] = ib; idx[p] = ia;
                }
            }
            __syncthreads();
        }
    }
    order[b * LS_ + t] = idx[t];
}

// ---------------- gather ----------------
__global__ __launch_bounds__(256)
void gather_kernel(const float* __restrict__ X1, const int* __restrict__ ord,
                   float* __restrict__ X2)
{
    int b = blockIdx.x, t = blockIdx.y;
    int src = (t < LT_) ? t : (LT_ + ord[b * LS_ + (t - LT_)]);
    const float* s = X1 + ((long long)b * NTOK + src) * DIM_;
    float* d = X2 + ((long long)b * N2 + t) * DIM_;
    int i = threadIdx.x;
    d[i] = s[i];
    d[i + 256] = s[i + 256];
    d[i + 512] = s[i + 512];
}

// ---------------- index outputs ----------------
__global__ __launch_bounds__(256)
void indices_kernel(const int* __restrict__ ord, const int* __restrict__ gsi,
                    float* __restrict__ outK, float* __restrict__ outR)
{
    int b = blockIdx.x, t = threadIdx.x;
    if (t < LK_) outK[b * LK_ + t] = (float)gsi[b * LS_ + ord[b * LS_ + t]];
    if (t < LR_) outR[b * LR_ + t] = (float)gsi[b * LS_ + ord[b * LS_ + LK_ + t]];
}

__global__ __launch_bounds__(256)
void git_kernel(const int* __restrict__ git, float* __restrict__ out)
{
    int i = blockIdx.x * 256 + threadIdx.x;
    if (i < B_ * LT_) out[i] = (float)git[i];
}

// ---------------- host orchestration ----------------
static void run_branch(const float* x, const int* gsi, const unsigned char* mask,
                       const float* g1, const float* b1,
                       const float* Wqkv, const float* bqkv,
                       const float* Wproj, const float* bproj,
                       const float* g2, const float* b2,
                       const float* W1, const float* bm1,
                       const float* W2, const float* bm2,
                       float* outX, float* outK, float* outR,
                       float* XLN, float* QKV, float* ATTN, float* O, float* X1,
                       float* S, int* ORD, float* X2, float* XLN2, float* H1m)
{
    // LN1
    ln_kernel<<<B_ * NTOK, 256>>>(x, g1, b1, XLN);

    // q = XLN @ Wqkv[:, 0:768] + bqkv[0:768]  (tensor core, split-bf16)
    tc_gemm<0><<<dim3(DIM_ / 128, B_ * NTOK / 128), TC_THREADS, TC_SMEM_TOTAL>>>(
        XLN, DIM_, Wqkv, 3 * DIM_, QKV, 3 * DIM_, bqkv, nullptr, 0, DIM_);
    // v = XLN @ Wqkv[:, 1536:2304] + bqkv[1536:]
    tc_gemm<0><<<dim3(DIM_ / 128, B_ * NTOK / 128), TC_THREADS, TC_SMEM_TOTAL>>>(
        XLN, DIM_, Wqkv + 2 * DIM_, 3 * DIM_, QKV + 2 * DIM_, 3 * DIM_,
        bqkv + 2 * DIM_, nullptr, 0, DIM_);

    // k (all rows): Kahan — score-path exact
    gemm_kernel<false, 0, true><<<dim3(DIM_ / BN, B_ * NTOK / BM, 1), 256>>>(
        XLN, DIM_, 0, 0,
        Wqkv + DIM_, 3 * DIM_, 0, 0,
        QKV + DIM_, 3 * DIM_, 0, 0,
        bqkv + DIM_, nullptr, 0, 0, 0,
        DIM_, 1, 1.0f);
    // q rows t<64 per batch: Kahan overwrite
    gemm_kernel<false, 0, true><<<dim3(DIM_ / BN, 1, B_), 256>>>(
        XLN, DIM_, 0, (long long)NTOK * DIM_,
        Wqkv, 3 * DIM_, 0, 0,
        QKV, 3 * DIM_, 0, (long long)NTOK * 3 * DIM_,
        bqkv, nullptr, 0, 0, 0,
        DIM_, B_, 1.0f);

    // logits rows 0..63 (score-critical): Kahan
    gemm_kernel<true, 0, true><<<dim3(NTOK / BN, 1, B_ * H_), 256>>>(
        QKV,        3 * DIM_, (long long)NTOK * 3 * DIM_, DH,
        QKV + DIM_, 3 * DIM_, (long long)NTOK * 3 * DIM_, DH,
        ATTN, NTOK, (long long)H_ * NTOK * NTOK, (long long)NTOK * NTOK,
        nullptr, nullptr, 0, 0, 0,
        DH, H_, 0.125f);
    // logits rows 64..319: plain
    gemm_kernel<true, 0, false><<<dim3(NTOK / BN, 4, B_ * H_), 256>>>(
        QKV + (long long)LT_ * 3 * DIM_, 3 * DIM_, (long long)NTOK * 3 * DIM_, DH,
        QKV + DIM_,                      3 * DIM_, (long long)NTOK * 3 * DIM_, DH,
        ATTN + (long long)LT_ * NTOK, NTOK, (long long)H_ * NTOK * NTOK, (long long)NTOK * NTOK,
        nullptr, nullptr, 0, 0, 0,
        DH, H_, 0.125f);

    softmax_kernel<<<B_ * H_ * NTOK, 128>>>(ATTN);

    // O = P @ V   per (b,h): [320 x 64, K=320]
    gemm_kernel<false, 0, false><<<dim3(DH / BN, NTOK / BM, B_ * H_), 256>>>(
        ATTN, NTOK, (long long)H_ * NTOK * NTOK, (long long)NTOK * NTOK,
        QKV + 2 * DIM_, 3 * DIM_, (long long)NTOK * 3 * DIM_, DH,
        O, DIM_, (long long)NTOK * DIM_, DH,
        nullptr, nullptr, 0, 0, 0,
        NTOK, H_, 1.0f);

    // X1 = x + O @ Wproj + bproj  (tensor core)
    tc_gemm<0><<<dim3(DIM_ / 128, B_ * NTOK / 128), TC_THREADS, TC_SMEM_TOTAL>>>(
        O, DIM_, Wproj, DIM_, X1, DIM_, bproj, x, DIM_, DIM_);

    // CE
    ce_score_kernel<<<B_, 256>>>(ATTN, mask, S);
    sort_kernel<<<B_, 256>>>(S, ORD);
    gather_kernel<<<dim3(B_, N2), 256>>>(X1, ORD, X2);
    indices_kernel<<<B_, 256>>>(ORD, gsi, outK, outR);

    // LN2
    ln_kernel<<<B_ * N2, 256>>>(X2, g2, b2, XLN2);

    // H1 = gelu(XLN2 @ W1 + bm1)   [7808 x 3072]  (tensor core)
    tc_gemm<1><<<dim3(4 * DIM_ / 128, B_ * N2 / 128), TC_THREADS, TC_SMEM_TOTAL>>>(
        XLN2, DIM_, W1, 4 * DIM_, H1m, 4 * DIM_, bm1, nullptr, 0, DIM_);

    // out = X2 + H1 @ W2 + bm2   [7808 x 768]  (tensor core)
    tc_gemm<0><<<dim3(DIM_ / 128, B_ * N2 / 128), TC_THREADS, TC_SMEM_TOTAL>>>(
        H1m, 4 * DIM_, W2, DIM_, outX, DIM_, bm2, X2, DIM_, 4 * DIM_);
}

extern "C" void kernel_launch(void* const* d_in, const int* in_sizes, int n_in,
                              void* d_out, int out_size)
{
    const float* x_rgb  = (const float*)d_in[0];
    const float* x_dte  = (const float*)d_in[1];
    const int*   git    = (const int*)d_in[2];
    const int*   gsi_rgb = (const int*)d_in[3];
    const int*   gsi_dte = (const int*)d_in[4];
    const unsigned char* mask = (const unsigned char*)d_in[5];
    const float* g1    = (const float*)d_in[6];
    const float* b1    = (const float*)d_in[7];
    const float* Wqkv  = (const float*)d_in[8];
    const float* bqkv  = (const float*)d_in[9];
    const float* Wproj = (const float*)d_in[10];
    const float* bproj = (const float*)d_in[11];
    const float* g2    = (const float*)d_in[12];
    const float* b2    = (const float*)d_in[13];
    const float* W1    = (const float*)d_in[14];
    const float* bm1   = (const float*)d_in[15];
    const float* W2    = (const float*)d_in[16];
    const float* bm2   = (const float*)d_in[17];

    float* out = (float*)d_out;

    // dynamic smem opt-in for the TC kernels (idempotent; not a stream op)
    cudaFuncSetAttribute(tc_gemm<0>, cudaFuncAttributeMaxDynamicSharedMemorySize, TC_SMEM_TOTAL);
    cudaFuncSetAttribute(tc_gemm<1>, cudaFuncAttributeMaxDynamicSharedMemorySize, TC_SMEM_TOTAL);

    float *XLN, *QKV, *ATTN, *O, *X1, *S, *X2, *XLN2, *H1m;
    int* ORD;
    cudaGetSymbolAddress((void**)&XLN,  g_XLN);
    cudaGetSymbolAddress((void**)&QKV,  g_QKV);
    cudaGetSymbolAddress((void**)&ATTN, g_ATTN);
    cudaGetSymbolAddress((void**)&O,    g_O);
    cudaGetSymbolAddress((void**)&X1,   g_X1);
    cudaGetSymbolAddress((void**)&S,    g_S);
    cudaGetSymbolAddress((void**)&ORD,  g_ORD);
    cudaGetSymbolAddress((void**)&X2,   g_X2);
    cudaGetSymbolAddress((void**)&XLN2, g_XLN2);
    cudaGetSymbolAddress((void**)&H1m,  g_H1);

    const long long XSZ     = (long long)B_ * N2 * DIM_;
    const long long GIT_OFF = 2 * XSZ;
    const long long K0_OFF  = GIT_OFF + (long long)B_ * LT_;
    const long long K1_OFF  = K0_OFF + (long long)B_ * LK_;
    const long long R0_OFF  = K1_OFF + (long long)B_ * LK_;
    const long long R1_OFF  = R0_OFF + (long long)B_ * LR_;

    git_kernel<<<(B_ * LT_ + 255) / 256, 256>>>(git, out + GIT_OFF);

    run_branch(x_rgb, gsi_rgb, mask, g1, b1, Wqkv, bqkv, Wproj, bproj, g2, b2,
               W1, bm1, W2, bm2,
               out, out + K0_OFF, out + R0_OFF,
               XLN, QKV, ATTN, O, X1, S, ORD, X2, XLN2, H1m);

    run_branch(x_dte, gsi_dte, mask, g1, b1, Wqkv, bqkv, Wproj, bproj, g2, b2,
               W1, bm1, W2, bm2,
               out + XSZ, out + K1_OFF, out + R1_OFF,
               XLN, QKV, ATTN, O, X1, S, ORD, X2, XLN2, H1m);
}